// round 17
// baseline (speedup 1.0000x reference)
#include <cuda_runtime.h>
#include <cuda_fp16.h>

#define HDIM   256
#define TPB    512
#define SB     264        // h row stride (fp16 elems)
#define TPAD   264        // c-table row stride (f32)
#define XSTR   10         // xbuf lane stride (floats); MUST be even (float2 exchange)
#define XHALF  (8 * 32 * XSTR)        // one dest-half of xbuf (floats)
#define XPAR   (2 * XHALF)            // one parity copy of xbuf (floats)
#define LN_EPS 1e-5f

// gamma-folded W_update in mma B-fragment lane order, fp16, uint4-packed:
// index (kt*16 + ntp)*32 + lane -> {nt0.r0, nt0.r1, nt1.r0, nt1.r1}
__device__ uint4 gBh[16 * 16 * 32];
// c-tables: rows 0..9 = c2[d] = emb(d)@W ; row 10 = c1 = gamma@W ; row 11 = c3 = beta@W + b_up
__device__ float gCtab[12 * 256];

__device__ __forceinline__ unsigned packh(float a, float b) {
    __half2 t = __floats2half2_rn(a, b);
    return *reinterpret_cast<unsigned*>(&t);
}
// HW tanh (MUFU.TANH): validated R15/R16 (rel_err 6.08e-4).
__device__ __forceinline__ float tanh_hw(float x) {
    float y;
    asm("tanh.approx.f32 %0, %1;" : "=f"(y) : "f"(x));
    return y;
}
__device__ __forceinline__ unsigned smem_u32(const void* p) {
    unsigned r;
    asm("{ .reg .u64 t; cvta.to.shared.u64 t, %1; cvt.u32.u64 %0, t; }" : "=r"(r) : "l"(p));
    return r;
}
__device__ __forceinline__ void ldmatrix_x4(unsigned a[4], unsigned addr) {
    asm volatile("ldmatrix.sync.aligned.m8n8.x4.shared.b16 {%0,%1,%2,%3}, [%4];"
                 : "=r"(a[0]), "=r"(a[1]), "=r"(a[2]), "=r"(a[3]) : "r"(addr));
}
__device__ __forceinline__ void mma_f16(float c[4], const unsigned a[4],
                                        unsigned b0, unsigned b1) {
    asm volatile("mma.sync.aligned.m16n8k16.row.col.f32.f16.f16.f32 "
                 "{%0,%1,%2,%3}, {%4,%5,%6,%7}, {%8,%9}, {%0,%1,%2,%3};"
                 : "+f"(c[0]), "+f"(c[1]), "+f"(c[2]), "+f"(c[3])
                 : "r"(a[0]), "r"(a[1]), "r"(a[2]), "r"(a[3]), "r"(b0), "r"(b1));
}
__device__ __forceinline__ void nbar_sync(int id) {
    asm volatile("bar.sync %0, %1;" :: "r"(id), "r"(512) : "memory");
}
__device__ __forceinline__ void nbar_arrive(int id) {
    asm volatile("bar.arrive %0, %1;" :: "r"(id), "r"(512) : "memory");
}

// ---------- single prep launch: blocks 0-31 pack W, block 32 builds c-tables ----------
__global__ void prep_all(const float* __restrict__ W,
                         const float* __restrict__ gamma,
                         const float* __restrict__ W_embed,
                         const float* __restrict__ b_embed,
                         const float* __restrict__ b_up,
                         const float* __restrict__ beta) {
    if (blockIdx.x < 32) {
        int idx = blockIdx.x * 256 + threadIdx.x;        // (kt, ntp, l): 16*16*32
        int kt  = idx >> 9;
        int ntp = (idx >> 5) & 15;
        int l   = idx & 31;
        unsigned hi[4];
        #pragma unroll
        for (int s = 0; s < 2; s++) {
            int nt = 2 * ntp + s;
            int n  = nt * 8 + (l >> 2);
            int k0 = kt * 16 + (l & 3) * 2;
            hi[s * 2 + 0] = packh(W[(k0 + 0) * HDIM + n] * gamma[k0 + 0],
                                  W[(k0 + 1) * HDIM + n] * gamma[k0 + 1]);
            hi[s * 2 + 1] = packh(W[(k0 + 8) * HDIM + n] * gamma[k0 + 8],
                                  W[(k0 + 9) * HDIM + n] * gamma[k0 + 9]);
        }
        gBh[(kt * 16 + ntp) * 32 + l] = make_uint4(hi[0], hi[1], hi[2], hi[3]);
    } else {
        __shared__ float e[10][256];
        __shared__ float gsh[256], btsh[256];
        int n = threadIdx.x;
        #pragma unroll
        for (int d = 0; d < 10; d++)
            e[d][n] = tanhf((float)d * W_embed[n] + b_embed[n]);
        gsh[n]  = gamma[n];
        btsh[n] = beta[n];
        __syncthreads();

        float acc[12];
        #pragma unroll
        for (int i = 0; i < 12; i++) acc[i] = 0.f;
        #pragma unroll 4
        for (int k = 0; k < 256; k++) {
            float wv = W[k * 256 + n];                   // coalesced
            #pragma unroll
            for (int d = 0; d < 10; d++) acc[d] = fmaf(e[d][k], wv, acc[d]);
            acc[10] = fmaf(gsh[k],  wv, acc[10]);
            acc[11] = fmaf(btsh[k], wv, acc[11]);
        }
        acc[11] += b_up[n];
        #pragma unroll
        for (int i = 0; i < 12; i++) gCtab[i * 256 + n] = acc[i];
    }
}

// ---------- main persistent scan: 1 block = 16 batch rows ----------
__global__ void __launch_bounds__(TPB, 1)
rnn_scan_kernel(const float* __restrict__ x,        // [B, T, 1]
                const float* __restrict__ b_up,     // [H]
                const float* __restrict__ gamma,    // [H]
                const float* __restrict__ beta,     // [H]
                const float* __restrict__ W_out,    // [H, 10]
                const float* __restrict__ b_out,    // [10]
                float* __restrict__ out,            // [B, 10]
                int B, int T)
{
    extern __shared__ unsigned char smem_raw[];
    float* tMain = (float*)smem_raw;                      // [10][TPAD]  c2[d]+c3
    float* tZero = tMain + 10 * TPAD;                     // [10][TPAD]  c2[d]+b_up
    float* gS    = tZero + 10 * TPAD;                     // [256] (output head)
    float* btS   = gS + 256;                              // [256]
    float* xbuf  = btS + 256;                             // [2 par][2 dest][8][32][XSTR]
    float* pSum  = xbuf + XPAR * 2;                       // [2 par][128]
    float* pSq   = pSum + 256;                            // [2 par][128]
    unsigned short* sHi = (unsigned short*)(pSq + 256);   // [16][SB] fp16 h
    unsigned char*  xiT = (unsigned char*)(sHi + 16 * SB);// [T][16]

    const int tid = threadIdx.x;
    const int w   = tid >> 5;
    const int l   = tid & 31;
    const int wc  = w & 7;                                // cols [32wc, 32wc+32)
    const int kh  = w >> 3;                               // k half
    const int b0  = blockIdx.x * 16;
    const int barArr = 3 + (wc >> 2);                     // producer barrier id
    const int barGate = 3 + kh;                           // consumer barrier id

    unsigned* sHiU = (unsigned*)sHi;

    const uint4* hiP0 = gBh + ((kh * 8) * 16 + 2 * wc) * 32 + l;
    const uint4* hiP1 = hiP0 + 32;

    // ---- one-time tables ----
    for (int idx = tid; idx < 10 * HDIM; idx += TPB) {
        int d  = idx / HDIM;
        int hh = idx - d * HDIM;
        float base = gCtab[d * 256 + hh];
        tMain[d * TPAD + hh] = base + gCtab[11 * 256 + hh];
        tZero[d * TPAD + hh] = base + b_up[hh];
    }
    for (int idx = tid; idx < HDIM; idx += TPB) {
        gS[idx]  = gamma[idx];
        btS[idx] = beta[idx];
    }
    for (int idx = tid; idx < 16 * T; idx += TPB) {
        int t = idx >> 4, m = idx & 15;
        xiT[t * 16 + m] = (unsigned char)__float2int_rn(x[(size_t)(b0 + m) * T + t]);
    }
    // zero-init h (t=0 GEMM then yields exactly P=0)
    for (int idx = tid; idx < 16 * 132; idx += TPB) sHiU[idx] = 0u;

    // ---- step-invariant c1 values for this lane's 8 columns (registers) ----
    float2 c1r[4];
    #pragma unroll
    for (int nti = 0; nti < 4; nti++)
        c1r[nti] = *(const float2*)(gCtab + 10 * 256 + 32 * wc + 8 * nti + 2 * (l & 3));
    __syncthreads();
    // seed producer arrivals so the t=0 gate passes (sHi zero-init above)
    nbar_arrive(barArr);

    const int rr = (l >> 2) + kh * 8;                     // lane's row after exchange
    const int q4 = l & 3;

    const int rowA  = (l & 7) + 8 * ((l >> 3) & 1);
    const int colbA = 8 * (l >> 4);
    const unsigned aHiBase = smem_u32(sHi) + (unsigned)(rowA * SB + colbA) * 2u
                           + (unsigned)(kh * 8) * 32u;

    float* xA = xbuf;                                     // kh1 -> kh0 (rows 0-7)
    float* xB = xbuf + XHALF;                             // kh0 -> kh1 (rows 8-15)
    float* xMineW = (kh ? xA : xB) + (wc * 32 + l) * XSTR;
    float* xMineR = (kh ? xB : xA) + (wc * 32 + l) * XSTR;

    for (int t = 0; t < T; t++) {
        const int par = t & 1;

        // ---- gate: this warp's A column-half of h(t-1) is ready ----
        nbar_sync(barGate);

        // ---------------- GEMM: P_partial = h(t-1) @ (gamma.W) over this k-half ----
        float acc[4][4];
        #pragma unroll
        for (int i = 0; i < 4; i++)
            #pragma unroll
            for (int p = 0; p < 4; p++) acc[i][p] = 0.f;

        uint4 h0[2], h1[2];
        unsigned aH[2][4];
        h0[0] = __ldg(hiP0);
        h1[0] = __ldg(hiP1);
        ldmatrix_x4(aH[0], aHiBase);

        #pragma unroll
        for (int kk = 0; kk < 8; kk++) {
            const int cur = kk & 1, nxt = cur ^ 1;
            if (kk < 7) {
                h0[nxt] = __ldg(hiP0 + (kk + 1) * 512);
                h1[nxt] = __ldg(hiP1 + (kk + 1) * 512);
                ldmatrix_x4(aH[nxt], aHiBase + (unsigned)(kk + 1) * 32u);
            }
            mma_f16(acc[0], aH[cur], h0[cur].x, h0[cur].y);
            mma_f16(acc[1], aH[cur], h0[cur].z, h0[cur].w);
            mma_f16(acc[2], aH[cur], h1[cur].x, h1[cur].y);
            mma_f16(acc[3], aH[cur], h1[cur].z, h1[cur].w);
        }

        // ---- row-split K exchange into parity buffer ----
        float* xw = xMineW + par * XPAR;
        #pragma unroll
        for (int nti = 0; nti < 4; nti++) {
            float2 snd = kh ? make_float2(acc[nti][0], acc[nti][1])
                            : make_float2(acc[nti][2], acc[nti][3]);
            *(float2*)(xw + nti * 2) = snd;
        }
        __syncthreads();                                   // bar1 (full; bounds skew)

        // ---- stats of h(t-1): coop LDS.32 + quad shfl (ping-pong buffer) ----
        float mu = 0.f, rs = 0.f;
        if (t) {
            const float* pS = pSum + (par ^ 1) * 128;
            const float* pQ = pSq  + (par ^ 1) * 128;
            float sm = pS[rr * 8 + q4] + pS[rr * 8 + 4 + q4];
            float qq = pQ[rr * 8 + q4] + pQ[rr * 8 + 4 + q4];
            sm += __shfl_xor_sync(0xffffffffu, sm, 1);
            sm += __shfl_xor_sync(0xffffffffu, sm, 2);
            qq += __shfl_xor_sync(0xffffffffu, qq, 1);
            qq += __shfl_xor_sync(0xffffffffu, qq, 2);
            mu = sm * (1.0f / HDIM);
            rs = rsqrtf(qq * (1.0f / HDIM) - mu * mu + LN_EPS);
        }
        const float nrm = -rs * mu;
        const float* trow = (t ? tMain : tZero) + (int)xiT[t * 16 + rr] * TPAD;
        const float* xr = xMineR + par * XPAR;

        float sum = 0.f, sq = 0.f;
        #pragma unroll
        for (int nti = 0; nti < 4; nti++) {
            float2 o = *(const float2*)(xr + nti * 2);
            float P0 = (kh ? acc[nti][2] : acc[nti][0]) + o.x;
            float P1 = (kh ? acc[nti][3] : acc[nti][1]) + o.y;

            int c0 = 32 * wc + 8 * nti + 2 * q4;
            float2 c2v = *(const float2*)(trow + c0);

            float v0 = fmaf(rs, P0, fmaf(nrm, c1r[nti].x, c2v.x));
            float v1 = fmaf(rs, P1, fmaf(nrm, c1r[nti].y, c2v.y));
            float hv0 = tanh_hw(v0);
            float hv1 = tanh_hw(v1);

            sum += hv0 + hv1;
            sq  += hv0 * hv0 + hv1 * hv1;

            sHiU[rr * 132 + (c0 >> 1)] = packh(hv0, hv1);
        }
        sum += __shfl_xor_sync(0xffffffffu, sum, 1);
        sum += __shfl_xor_sync(0xffffffffu, sum, 2);
        sq  += __shfl_xor_sync(0xffffffffu, sq, 1);
        sq  += __shfl_xor_sync(0xffffffffu, sq, 2);
        if (q4 == 0) {
            pSum[par * 128 + rr * 8 + wc] = sum;
            pSq [par * 128 + rr * 8 + wc] = sq;
        }

        // ---- producer arrival: my h columns are stored ----
        nbar_arrive(barArr);
    }
    __syncthreads();                                       // all epilogue(T-1) done

    // ---- output head: h_ln = (h - mu)*rs*gamma + beta, then @W_out + b_out ----
    if (tid < 160) {
        int m  = tid / 10;
        int cx = tid - m * 10;
        const float* pS = pSum + ((T - 1) & 1) * 128;
        const float* pQ = pSq  + ((T - 1) & 1) * 128;
        float sm = 0.f, qq = 0.f;
        #pragma unroll
        for (int i = 0; i < 8; i++) { sm += pS[m * 8 + i]; qq += pQ[m * 8 + i]; }
        float mu = sm * (1.0f / HDIM);
        float rs = rsqrtf(qq * (1.0f / HDIM) - mu * mu + LN_EPS);

        const __half* rh = (const __half*)sHi + m * SB;
        float a = b_out[cx];
        #pragma unroll 8
        for (int k = 0; k < HDIM; k++) {
            float h  = __half2float(rh[k]);
            float hl = (h - mu) * rs * gS[k] + btS[k];
            a = fmaf(hl, __ldg(W_out + k * 10 + cx), a);
        }
        out[(size_t)(b0 + m) * 10 + cx] = a;
    }
}

extern "C" void kernel_launch(void* const* d_in, const int* in_sizes, int n_in,
                              void* d_out, int out_size)
{
    const float* x       = (const float*)d_in[0];
    const float* W_embed = (const float*)d_in[1];
    const float* b_embed = (const float*)d_in[2];
    const float* W_up    = (const float*)d_in[3];
    const float* b_up    = (const float*)d_in[4];
    const float* gamma   = (const float*)d_in[5];
    const float* beta    = (const float*)d_in[6];
    const float* W_out   = (const float*)d_in[7];
    const float* b_out   = (const float*)d_in[8];
    float* out = (float*)d_out;

    int B = out_size / 10;          // 2048
    int T = in_sizes[0] / B;        // 512

    prep_all<<<33, 256>>>(W_up, gamma, W_embed, b_embed, b_up, beta);

    size_t smem = (size_t)2 * 10 * TPAD * 4      // tMain + tZero
                + 2 * 256 * 4                    // gS, btS
                + (size_t)XPAR * 2 * 4           // xbuf (ping-pong)
                + 2 * 256 * 4                    // pSum/pSq (ping-pong)
                + (size_t)16 * SB * 2            // sHi
                + (size_t)16 * T                 // xiT
                + 64;
    cudaFuncSetAttribute(rnn_scan_kernel,
                         cudaFuncAttributeMaxDynamicSharedMemorySize, (int)smem);
    rnn_scan_kernel<<<B / 16, TPB, smem>>>(x, b_up, gamma, beta,
                                           W_out, b_out, out, B, T);
}